// round 16
// baseline (speedup 1.0000x reference)
#include <cuda_runtime.h>
#include <cooperative_groups.h>

namespace cg = cooperative_groups;

// Problem constants (fixed by the dataset): B=2, N=64, CI=32, CO=32
#define B2 2
#define NP 64
#define CIc 32
#define COc 32
#define CLU 8                        // cluster size = blocks per z
#define ROWS_PB (NP * NP / CLU)      // 512 rows per block

// ---------------------------------------------------------------------------
// Single fused kernel: grid = 16 blocks, clusters of 8 (one cluster per z).
// Phase 1: per-block weighted feature reduction -> own smem partials.
// cluster.sync -> DSMEM all-gather reduce -> contraction -> 8 output rows.
// ---------------------------------------------------------------------------
__global__ void __launch_bounds__(256, 1) __cluster_dims__(CLU, 1, 1)
pc_all(const float* __restrict__ f,
       const float* __restrict__ geom,
       const float* __restrict__ W,
       const void*  __restrict__ nnp,
       float* __restrict__ out)
{
    cg::cluster_group cluster = cg::this_cluster();

    int z    = blockIdx.x >> 3;
    int g    = blockIdx.x & 7;       // rank within cluster; c-range = g*8..g*8+7
    int tid  = threadIdx.x;
    int lane = tid & 31;
    int w    = tid >> 5;

    __shared__ float gsh[NP][3];
    __shared__ float shred[8][7][CIc];
    __shared__ __align__(16) float red_p[7][CIc];   // this block's partials (peers read!)
    __shared__ __align__(16) float redS[7][CIc];    // cluster-summed reductions
    __shared__ __align__(16) float Aa[3][COc], Ab[3][COc], Cst[3][COc];
    __shared__ __align__(16) float UaS[8][COc];

    // ---- Prologue: geometry to smem, n_norm scale ------------------------
    for (int t = tid; t < NP * 3; t += 256)
        gsh[t / 3][t % 3] = geom[z * NP * 3 + t];

    int   iv = *(const int*)nnp;
    float nn = (iv >= 1 && iv <= (1 << 20)) ? (float)iv : *(const float*)nnp;
    float s  = rsqrtf(6.0f * nn * nn);
    __syncthreads();

    // ---- Phase 1: reduce this block's 512 rows ---------------------------
    // Thread's rows: rr = w + 64*ko + 8*m  (ko,m in 0..7)
    //   c = g*8 + ko  (constant over m),  d = w + 8*m  (constant over ko)
    int r0 = g * ROWS_PB;
    const float* base = f + ((size_t)z * NP * NP + r0) * CIc + lane;

    float cs[8] = {0, 0, 0, 0, 0, 0, 0, 0};        // per-d-residue sums
    float ft = 0.f, s1 = 0.f, s2 = 0.f, s3 = 0.f;  // ft, GFs partials
    #pragma unroll
    for (int ko = 0; ko < 8; ko++) {
        int c = g * 8 + ko;
        float rs = 0.f;
        #pragma unroll
        for (int m = 0; m < 8; m++) {
            float v = base[(w + 64 * ko + 8 * m) * CIc];   // coalesced
            rs += v;
            cs[m] += v;
        }
        ft += rs;
        s1 += rs * gsh[c][0];
        s2 += rs * gsh[c][1];
        s3 += rs * gsh[c][2];
    }
    float s4 = 0.f, s5 = 0.f, s6 = 0.f;            // GFd partials
    #pragma unroll
    for (int m = 0; m < 8; m++) {
        int d = w + 8 * m;
        s4 += cs[m] * gsh[d][0];
        s5 += cs[m] * gsh[d][1];
        s6 += cs[m] * gsh[d][2];
    }

    // Prefetch W into registers (L2); overlaps the smem reduce + sync below.
    float4 Wr[6][8];
    if (tid < 96) {
        int x = tid >> 5, i = tid & 31;
        const float4* Wb = reinterpret_cast<const float4*>(
            W + (size_t)x * (6 * COc * CIc) + i * CIc);
        #pragma unroll
        for (int mm = 0; mm < 6; mm++)
            #pragma unroll
            for (int q = 0; q < 8; q++)
                Wr[mm][q] = Wb[mm * 256 + q];
    }

    shred[w][0][lane] = ft; shred[w][1][lane] = s1; shred[w][2][lane] = s2;
    shred[w][3][lane] = s3; shred[w][4][lane] = s4; shred[w][5][lane] = s5;
    shred[w][6][lane] = s6;
    __syncthreads();
    if (tid < 224) {
        int t = tid >> 5;                          // 0..6
        float acc = 0.f;
        #pragma unroll
        for (int k = 0; k < 8; k++) acc += shred[k][t][lane];
        red_p[t][lane] = acc;
    }

    // ---- Cluster barrier #1: all partials visible ------------------------
    cluster.sync();

    // ---- DSMEM all-gather reduce: sum 8 ranks' partials ------------------
    if (tid < 224) {
        int t = tid >> 5;
        float acc = 0.f;
        #pragma unroll
        for (int r = 0; r < CLU; r++) {
            const float* peer = cluster.map_shared_rank(&red_p[t][lane], r);
            acc += *peer;
        }
        redS[t][lane] = acc;
    }

    // ---- Cluster barrier #2: peer smem reads complete before any exit ----
    cluster.sync();

    // ---- Contraction: per-thread (x,i) dot products over j ---------------
    if (tid < 96) {
        int x = tid >> 5, i = tid & 31;
        const float4* ftv = reinterpret_cast<const float4*>(&redS[0][0]);
        const float4* gsv = reinterpret_cast<const float4*>(&redS[1 + x][0]);
        const float4* gdv = reinterpret_cast<const float4*>(&redS[4 + x][0]);
        float aa = 0.f, ab = 0.f, cc = 0.f;
        #pragma unroll
        for (int q = 0; q < 8; q++) {
            float4 w1 = Wr[0][q], w2 = Wr[1][q], w3 = Wr[2][q];
            float4 w4 = Wr[3][q], w5 = Wr[4][q], w6 = Wr[5][q];
            float4 ft4 = ftv[q], gs4 = gsv[q], gd4 = gdv[q];
            aa += (w1.x + w2.x + w3.x) * ft4.x + (w1.y + w2.y + w3.y) * ft4.y
                + (w1.z + w2.z + w3.z) * ft4.z + (w1.w + w2.w + w3.w) * ft4.w;
            ab += (w1.x - w4.x - w5.x) * ft4.x + (w1.y - w4.y - w5.y) * ft4.y
                + (w1.z - w4.z - w5.z) * ft4.z + (w1.w - w4.w - w5.w) * ft4.w;
            cc += (w2.x + w4.x) * gs4.x + (w3.x + w5.x) * gd4.x + w6.x * (gd4.x - gs4.x)
                + (w2.y + w4.y) * gs4.y + (w3.y + w5.y) * gd4.y + w6.y * (gd4.y - gs4.y)
                + (w2.z + w4.z) * gs4.z + (w3.z + w5.z) * gd4.z + w6.z * (gd4.z - gs4.z)
                + (w2.w + w4.w) * gs4.w + (w3.w + w5.w) * gd4.w + w6.w * (gd4.w - gs4.w);
        }
        Aa[x][i] = aa;
        Ab[x][i] = ab * s;                          // pre-scaled
        Cst[x][i] = cc;
    }
    __syncthreads();

    // ---- Ua for this block's 8 rows (a = g*8 .. g*8+7) -------------------
    {
        int al = tid >> 5;                          // 0..7 (all 256 threads)
        int i  = lane;
        int a  = g * 8 + al;
        float cv = s * (Cst[0][i] + Cst[1][i] + Cst[2][i]);
        float g0 = gsh[a][0], g1 = gsh[a][1], g2 = gsh[a][2];
        UaS[al][i] = cv - s * (g0 * Aa[0][i] + g1 * Aa[1][i] + g2 * Aa[2][i]);
    }
    __syncthreads();

    // ---- Epilogue: out[z,a,b,i] = Ua[a,i] + <g_b, Ab[:,i]> ---------------
    {
        const float4* ab04 = reinterpret_cast<const float4*>(&Ab[0][0]);
        const float4* ab14 = reinterpret_cast<const float4*>(&Ab[1][0]);
        const float4* ab24 = reinterpret_cast<const float4*>(&Ab[2][0]);
        float4* o = reinterpret_cast<float4*>(
            out + ((size_t)(z * NP + g * 8) * NP) * COc);
        #pragma unroll
        for (int slot = tid; slot < 8 * NP * 8; slot += 256) {
            int al  = slot >> 9;                    // 0..7
            int rem = slot & 511;
            int b   = rem >> 3, q = rem & 7;
            const float4* ua4 = reinterpret_cast<const float4*>(&UaS[al][0]);
            float gb0 = gsh[b][0], gb1 = gsh[b][1], gb2 = gsh[b][2];
            float4 u = ua4[q], v0 = ab04[q], v1 = ab14[q], v2 = ab24[q];
            float4 r;
            r.x = u.x + gb0 * v0.x + gb1 * v1.x + gb2 * v2.x;
            r.y = u.y + gb0 * v0.y + gb1 * v1.y + gb2 * v2.y;
            r.z = u.z + gb0 * v0.z + gb1 * v1.z + gb2 * v2.z;
            r.w = u.w + gb0 * v0.w + gb1 * v1.w + gb2 * v2.w;
            o[slot] = r;
        }
    }
}

// ---------------------------------------------------------------------------
extern "C" void kernel_launch(void* const* d_in, const int* in_sizes, int n_in,
                              void* d_out, int out_size) {
    const float* features = (const float*)d_in[0]; // [2,64,64,32]
    const float* geometry = (const float*)d_in[1]; // [2,64,3]
    const float* W        = (const float*)d_in[2]; // [3,6144]
    const void*  n_norm   = d_in[3];               // scalar
    float* out = (float*)d_out;                    // [2,64,64,32]

    // Static __cluster_dims__(8): plain launch, grid 16 = 2 clusters (one per z)
    pc_all<<<B2 * CLU, 256>>>(features, geometry, W, n_norm, out);
}

// round 17
// speedup vs baseline: 1.0151x; 1.0151x over previous
#include <cuda_runtime.h>
#include <cooperative_groups.h>

namespace cg = cooperative_groups;

// Problem constants (fixed by the dataset): B=2, N=64, CI=32, CO=32
#define B2 2
#define NP 64
#define CIc 32
#define COc 32
#define CLU 8                        // cluster size = blocks per z
#define ROWS_PB (NP * NP / CLU)      // 512 rows per block

#define CLUSTER_ARRIVE() asm volatile("barrier.cluster.arrive.aligned;" ::: "memory")
#define CLUSTER_WAIT()   asm volatile("barrier.cluster.wait.aligned;"   ::: "memory")

// ---------------------------------------------------------------------------
// Single fused kernel: grid = 16 blocks, clusters of 8 (one cluster per z).
// Phase 1: per-block weighted feature reduction -> own smem partials.
// cluster barrier -> DSMEM all-gather reduce -> (arrive early) -> contraction
// split over 192 threads -> epilogue -> (wait last).
// ---------------------------------------------------------------------------
__global__ void __launch_bounds__(256, 1) __cluster_dims__(CLU, 1, 1)
pc_all(const float* __restrict__ f,
       const float* __restrict__ geom,
       const float* __restrict__ W,
       const void*  __restrict__ nnp,
       float* __restrict__ out)
{
    cg::cluster_group cluster = cg::this_cluster();

    int z    = blockIdx.x >> 3;
    int g    = blockIdx.x & 7;       // rank within cluster; c-range = g*8..g*8+7
    int tid  = threadIdx.x;
    int lane = tid & 31;
    int w    = tid >> 5;

    __shared__ float gsh[NP][3];
    __shared__ float shred[8][7][CIc];
    __shared__ __align__(16) float red_p[7][CIc];   // this block's partials (peers read!)
    __shared__ __align__(16) float redS[7][CIc];    // cluster-summed reductions
    __shared__ __align__(16) float Aa[3][COc], Ab[3][COc], Cst[3][COc];
    __shared__ float P_aa[2][96], P_ab[2][96], P_cc[2][96];
    __shared__ __align__(16) float UaS[8][COc];

    // ---- Prologue: geometry to smem, n_norm scale ------------------------
    for (int t = tid; t < NP * 3; t += 256)
        gsh[t / 3][t % 3] = geom[z * NP * 3 + t];

    int   iv = *(const int*)nnp;
    float nn = (iv >= 1 && iv <= (1 << 20)) ? (float)iv : *(const float*)nnp;
    float s  = rsqrtf(6.0f * nn * nn);

    // Prefetch W into registers (L2). tid<192: thread (pair,half) needs its
    // 4 q-slots of all 6 matrices. Issued before phase 1 to maximize overlap.
    float4 Wr[6][4];
    int pair = (tid >= 96) ? tid - 96 : tid;        // 0..95
    int half = (tid >= 96) ? 1 : 0;                 // q in [4*half, 4*half+4)
    if (tid < 192) {
        int x = pair >> 5, i = pair & 31;
        const float4* Wb = reinterpret_cast<const float4*>(
            W + (size_t)x * (6 * COc * CIc) + i * CIc) + half * 4;
        #pragma unroll
        for (int mm = 0; mm < 6; mm++)
            #pragma unroll
            for (int q = 0; q < 4; q++)
                Wr[mm][q] = Wb[mm * 256 + q];
    }
    __syncthreads();

    // ---- Phase 1: reduce this block's 512 rows ---------------------------
    // Thread's rows: rr = w + 64*ko + 8*m  (ko,m in 0..7)
    //   c = g*8 + ko  (constant over m),  d = w + 8*m  (constant over ko)
    int r0 = g * ROWS_PB;
    const float* base = f + ((size_t)z * NP * NP + r0) * CIc + lane;

    float cs[8] = {0, 0, 0, 0, 0, 0, 0, 0};        // per-d-residue sums
    float ft = 0.f, s1 = 0.f, s2 = 0.f, s3 = 0.f;  // ft, GFs partials
    #pragma unroll
    for (int ko = 0; ko < 8; ko++) {
        int c = g * 8 + ko;
        float rs = 0.f;
        #pragma unroll
        for (int m = 0; m < 8; m++) {
            float v = base[(w + 64 * ko + 8 * m) * CIc];   // coalesced
            rs += v;
            cs[m] += v;
        }
        ft += rs;
        s1 += rs * gsh[c][0];
        s2 += rs * gsh[c][1];
        s3 += rs * gsh[c][2];
    }
    float s4 = 0.f, s5 = 0.f, s6 = 0.f;            // GFd partials
    #pragma unroll
    for (int m = 0; m < 8; m++) {
        int d = w + 8 * m;
        s4 += cs[m] * gsh[d][0];
        s5 += cs[m] * gsh[d][1];
        s6 += cs[m] * gsh[d][2];
    }

    shred[w][0][lane] = ft; shred[w][1][lane] = s1; shred[w][2][lane] = s2;
    shred[w][3][lane] = s3; shred[w][4][lane] = s4; shred[w][5][lane] = s5;
    shred[w][6][lane] = s6;
    __syncthreads();
    if (tid < 224) {
        int t = tid >> 5;                          // 0..6
        float acc = 0.f;
        #pragma unroll
        for (int k = 0; k < 8; k++) acc += shred[k][t][lane];
        red_p[t][lane] = acc;
    }
    __syncthreads();

    // ---- Cluster barrier #1: all partials visible (release/acquire) ------
    CLUSTER_ARRIVE();
    CLUSTER_WAIT();

    // ---- DSMEM all-gather reduce: sum 8 ranks' partials ------------------
    if (tid < 224) {
        int t = tid >> 5;
        float acc = 0.f;
        #pragma unroll
        for (int r = 0; r < CLU; r++) {
            const float* peer = cluster.map_shared_rank(&red_p[t][lane], r);
            acc += *peer;
        }
        redS[t][lane] = acc;
    }
    __syncthreads();

    // ---- Arrive NOW (my peer-smem reads are done); wait at kernel end ----
    CLUSTER_ARRIVE();

    // ---- Contraction: 192 threads, each (x,i) pair split into 2 j-halves -
    if (tid < 192) {
        const float4* ftv = reinterpret_cast<const float4*>(&redS[0][0]) + half * 4;
        int x = pair >> 5;
        const float4* gsv = reinterpret_cast<const float4*>(&redS[1 + x][0]) + half * 4;
        const float4* gdv = reinterpret_cast<const float4*>(&redS[4 + x][0]) + half * 4;
        float aa = 0.f, ab = 0.f, cc = 0.f;
        #pragma unroll
        for (int q = 0; q < 4; q++) {
            float4 w1 = Wr[0][q], w2 = Wr[1][q], w3 = Wr[2][q];
            float4 w4 = Wr[3][q], w5 = Wr[4][q], w6 = Wr[5][q];
            float4 ft4 = ftv[q], gs4 = gsv[q], gd4 = gdv[q];
            aa += (w1.x + w2.x + w3.x) * ft4.x + (w1.y + w2.y + w3.y) * ft4.y
                + (w1.z + w2.z + w3.z) * ft4.z + (w1.w + w2.w + w3.w) * ft4.w;
            ab += (w1.x - w4.x - w5.x) * ft4.x + (w1.y - w4.y - w5.y) * ft4.y
                + (w1.z - w4.z - w5.z) * ft4.z + (w1.w - w4.w - w5.w) * ft4.w;
            cc += (w2.x + w4.x) * gs4.x + (w3.x + w5.x) * gd4.x + w6.x * (gd4.x - gs4.x)
                + (w2.y + w4.y) * gs4.y + (w3.y + w5.y) * gd4.y + w6.y * (gd4.y - gs4.y)
                + (w2.z + w4.z) * gs4.z + (w3.z + w5.z) * gd4.z + w6.z * (gd4.z - gs4.z)
                + (w2.w + w4.w) * gs4.w + (w3.w + w5.w) * gd4.w + w6.w * (gd4.w - gs4.w);
        }
        P_aa[half][pair] = aa; P_ab[half][pair] = ab; P_cc[half][pair] = cc;
    }
    __syncthreads();

    if (tid < 96) {
        int x = tid >> 5, i = tid & 31;
        Aa[x][i]  = P_aa[0][tid] + P_aa[1][tid];
        Ab[x][i]  = (P_ab[0][tid] + P_ab[1][tid]) * s;   // pre-scaled
        Cst[x][i] = P_cc[0][tid] + P_cc[1][tid];
    }
    __syncthreads();

    // ---- Ua for this block's 8 rows (a = g*8 .. g*8+7) -------------------
    {
        int al = tid >> 5;                          // 0..7 (all 256 threads)
        int i  = lane;
        int a  = g * 8 + al;
        float cv = s * (Cst[0][i] + Cst[1][i] + Cst[2][i]);
        float g0 = gsh[a][0], g1 = gsh[a][1], g2 = gsh[a][2];
        UaS[al][i] = cv - s * (g0 * Aa[0][i] + g1 * Aa[1][i] + g2 * Aa[2][i]);
    }
    __syncthreads();

    // ---- Epilogue: out[z,a,b,i] = Ua[a,i] + <g_b, Ab[:,i]> ---------------
    {
        const float4* ab04 = reinterpret_cast<const float4*>(&Ab[0][0]);
        const float4* ab14 = reinterpret_cast<const float4*>(&Ab[1][0]);
        const float4* ab24 = reinterpret_cast<const float4*>(&Ab[2][0]);
        float4* o = reinterpret_cast<float4*>(
            out + ((size_t)(z * NP + g * 8) * NP) * COc);
        #pragma unroll
        for (int slot = tid; slot < 8 * NP * 8; slot += 256) {
            int al  = slot >> 9;                    // 0..7
            int rem = slot & 511;
            int b   = rem >> 3, q = rem & 7;
            const float4* ua4 = reinterpret_cast<const float4*>(&UaS[al][0]);
            float gb0 = gsh[b][0], gb1 = gsh[b][1], gb2 = gsh[b][2];
            float4 u = ua4[q], v0 = ab04[q], v1 = ab14[q], v2 = ab24[q];
            float4 r;
            r.x = u.x + gb0 * v0.x + gb1 * v1.x + gb2 * v2.x;
            r.y = u.y + gb0 * v0.y + gb1 * v1.y + gb2 * v2.y;
            r.z = u.z + gb0 * v0.z + gb1 * v1.z + gb2 * v2.z;
            r.w = u.w + gb0 * v0.w + gb1 * v1.w + gb2 * v2.w;
            o[slot] = r;
        }
    }

    // ---- Deferred wait: peer-smem lifetime pinned until everyone read ----
    CLUSTER_WAIT();
}

// ---------------------------------------------------------------------------
extern "C" void kernel_launch(void* const* d_in, const int* in_sizes, int n_in,
                              void* d_out, int out_size) {
    const float* features = (const float*)d_in[0]; // [2,64,64,32]
    const float* geometry = (const float*)d_in[1]; // [2,64,3]
    const float* W        = (const float*)d_in[2]; // [3,6144]
    const void*  n_norm   = d_in[3];               // scalar
    float* out = (float*)d_out;                    // [2,64,64,32]

    // Static __cluster_dims__(8): plain launch, grid 16 = 2 clusters (one per z)
    pc_all<<<B2 * CLU, 256>>>(features, geometry, W, n_norm, out);
}